// round 12
// baseline (speedup 1.0000x reference)
#include <cuda_runtime.h>
#include <cuda_bf16.h>
#include <cstdint>

// Problem constants
#define BB 2
#define TT 2048
#define CC 1024
#define HH 16
#define HD 64
#define MM (BB*TT)   // 4096 rows

// 0.125 (1/sqrt(64)) * log2(e), folded into Q projection
#define SCALE_Q 0.18033688f

// ---------------------------------------------------------------------------
// Scratch (__device__ globals: allocation-free rule)
// ---------------------------------------------------------------------------
__device__ __nv_bfloat16 g_Xh[(size_t)MM*CC];
__device__ __nv_bfloat16 g_Xl[(size_t)MM*CC];
__device__ __nv_bfloat16 g_Qh[(size_t)MM*CC];
__device__ __nv_bfloat16 g_Ql[(size_t)MM*CC];
__device__ __nv_bfloat16 g_Kh[(size_t)MM*CC];
__device__ __nv_bfloat16 g_Kl[(size_t)MM*CC];
__device__ __nv_bfloat16 g_Vth[(size_t)MM*CC];  // V transposed per head [b,h,d,t]
__device__ __nv_bfloat16 g_Vtl[(size_t)MM*CC];
__device__ __nv_bfloat16 g_Yh[(size_t)MM*CC];
__device__ __nv_bfloat16 g_Yl[(size_t)MM*CC];
__device__ __nv_bfloat16 g_Wth[(size_t)4*CC*CC];
__device__ __nv_bfloat16 g_Wtl[(size_t)4*CC*CC];

// ---------------------------------------------------------------------------
// PTX helpers
// ---------------------------------------------------------------------------
__device__ __forceinline__ uint32_t smem_u32(const void* p) {
    uint32_t a;
    asm("{ .reg .u64 t; cvta.to.shared.u64 t, %1; cvt.u32.u64 %0, t; }" : "=r"(a) : "l"(p));
    return a;
}
__device__ __forceinline__ void cp_async16(uint32_t saddr, const void* gaddr) {
    asm volatile("cp.async.ca.shared.global [%0], [%1], 16;" :: "r"(saddr), "l"(gaddr));
}
#define CP_COMMIT() asm volatile("cp.async.commit_group;" ::: "memory")

__device__ __forceinline__ void ldmat_x4(uint32_t* r, uint32_t addr) {
    asm volatile("ldmatrix.sync.aligned.m8n8.x4.shared.b16 {%0,%1,%2,%3}, [%4];"
        : "=r"(r[0]), "=r"(r[1]), "=r"(r[2]), "=r"(r[3]) : "r"(addr));
}
__device__ __forceinline__ void ldmat_x2(uint32_t* r, uint32_t addr) {
    asm volatile("ldmatrix.sync.aligned.m8n8.x2.shared.b16 {%0,%1}, [%2];"
        : "=r"(r[0]), "=r"(r[1]) : "r"(addr));
}
__device__ __forceinline__ void mma_bf16(float* c, const uint32_t* a, const uint32_t* b) {
    asm volatile("mma.sync.aligned.m16n8k16.row.col.f32.bf16.bf16.f32 "
        "{%0,%1,%2,%3}, {%4,%5,%6,%7}, {%8,%9}, {%0,%1,%2,%3};"
        : "+f"(c[0]), "+f"(c[1]), "+f"(c[2]), "+f"(c[3])
        : "r"(a[0]), "r"(a[1]), "r"(a[2]), "r"(a[3]), "r"(b[0]), "r"(b[1]));
}
__device__ __forceinline__ uint32_t pack_bf16x2(float lo, float hi) {
    uint32_t d;
    asm("cvt.rn.satfinite.bf16x2.f32 %0, %1, %2;" : "=r"(d) : "f"(hi), "f"(lo));
    return d;
}
__device__ __forceinline__ float ex2f(float x) {
    float y; asm("ex2.approx.f32 %0, %1;" : "=f"(y) : "f"(x)); return y;
}

// ---------------------------------------------------------------------------
// Split-precision conversion kernels
// ---------------------------------------------------------------------------
__device__ __forceinline__ void split_bf16(float v, __nv_bfloat16& h, __nv_bfloat16& l) {
    h = __float2bfloat16(v);
    l = __float2bfloat16(v - __bfloat162float(h));
}

__global__ void convert_split_kernel(const float* __restrict__ in,
                                     __nv_bfloat16* __restrict__ oh,
                                     __nv_bfloat16* __restrict__ ol, int n4)
{
    for (int i = blockIdx.x * blockDim.x + threadIdx.x; i < n4; i += gridDim.x * blockDim.x) {
        float4 v = ((const float4*)in)[i];
        __nv_bfloat16 h0,l0,h1,l1,h2,l2,h3,l3;
        split_bf16(v.x,h0,l0); split_bf16(v.y,h1,l1);
        split_bf16(v.z,h2,l2); split_bf16(v.w,h3,l3);
        ((__nv_bfloat162*)oh)[2*i]   = __halves2bfloat162(h0,h1);
        ((__nv_bfloat162*)oh)[2*i+1] = __halves2bfloat162(h2,h3);
        ((__nv_bfloat162*)ol)[2*i]   = __halves2bfloat162(l0,l1);
        ((__nv_bfloat162*)ol)[2*i+1] = __halves2bfloat162(l2,l3);
    }
}

// 4 weights W[K,N] -> Wt[N,K] split into hi/lo bf16; grid.z selects weight
__global__ void transpose_split_kernel(
    const float* __restrict__ W0, const float* __restrict__ W1,
    const float* __restrict__ W2, const float* __restrict__ W3,
    __nv_bfloat16* __restrict__ Th, __nv_bfloat16* __restrict__ Tl)
{
    __shared__ float t[32][33];
    const int z = blockIdx.z;
    const float* W = (z == 0) ? W0 : (z == 1) ? W1 : (z == 2) ? W2 : W3;
    __nv_bfloat16* Thz = Th + (size_t)z * CC * CC;
    __nv_bfloat16* Tlz = Tl + (size_t)z * CC * CC;
    int xi = blockIdx.x * 32 + threadIdx.x;
    int yi = blockIdx.y * 32 + threadIdx.y;
#pragma unroll
    for (int j = 0; j < 32; j += 8)
        t[threadIdx.y + j][threadIdx.x] = W[(size_t)(yi + j) * CC + xi];
    __syncthreads();
    int xo = blockIdx.y * 32 + threadIdx.x;
    int yo = blockIdx.x * 32 + threadIdx.y;
#pragma unroll
    for (int j = 0; j < 32; j += 8) {
        float v = t[threadIdx.x][threadIdx.y + j];
        __nv_bfloat16 h, l;
        split_bf16(v, h, l);
        Thz[(size_t)(yo + j) * CC + xo] = h;
        Tlz[(size_t)(yo + j) * CC + xo] = l;
    }
}

// ---------------------------------------------------------------------------
// GEMM core (device function): [4096,1024] = A @ Wt^T + bias, epilogue mode:
//   mode 0: fp32 row-major; mode 1: split bf16 row-major; mode 2: split + V-transpose
// ---------------------------------------------------------------------------
#define BK 32
#define PITCH 40
#define TILE_BYTES (128 * PITCH * 2)
#define AH_OFF 0
#define AL_OFF (2 * TILE_BYTES)
#define BH_OFF (4 * TILE_BYTES)
#define BL_OFF (6 * TILE_BYTES)
#define GEMM_SMEM (8 * TILE_BYTES)     // 81920 B

__device__ __forceinline__ void gemm_core(
    const __nv_bfloat16* __restrict__ Ah, const __nv_bfloat16* __restrict__ Al,
    const __nv_bfloat16* __restrict__ Bh, const __nv_bfloat16* __restrict__ Bl,
    const float* __restrict__ bias,
    float* __restrict__ outf,
    __nv_bfloat16* __restrict__ outh, __nv_bfloat16* __restrict__ outl,
    int mode, float scale, char* smem)
{
    const uint32_t sbase = smem_u32(smem);
    const int tid  = threadIdx.x;
    const int lane = tid & 31;
    const int wid  = tid >> 5;
    const int warp_m = wid >> 2;
    const int warp_n = wid & 3;

    const int rowBase = blockIdx.y * 128;
    const int colBase = blockIdx.x * 128;

    float acc[4][4][4];
#pragma unroll
    for (int i = 0; i < 4; i++)
#pragma unroll
        for (int j = 0; j < 4; j++)
#pragma unroll
            for (int r = 0; r < 4; r++) acc[i][j][r] = 0.f;

    auto load_stage = [&](int stg, int kc0) {
        const uint32_t so = (uint32_t)stg * TILE_BYTES;
#pragma unroll
        for (int it = 0; it < 2; it++) {
            int v = tid + it * 256;
            int r = v >> 2;
            int cv = v & 3;
            uint32_t doff = so + (uint32_t)(r * 80 + cv * 16);
            size_t gA = (size_t)(rowBase + r) * CC + kc0 + cv * 8;
            size_t gB = (size_t)(colBase + r) * CC + kc0 + cv * 8;
            cp_async16(sbase + AH_OFF + doff, Ah + gA);
            cp_async16(sbase + AL_OFF + doff, Al + gA);
            cp_async16(sbase + BH_OFF + doff, Bh + gB);
            cp_async16(sbase + BL_OFF + doff, Bl + gB);
        }
        CP_COMMIT();
    };

    const int arow  = (lane & 7) + ((lane >> 3) & 1) * 8;
    const int akoff = (lane >> 4) * 8;
    const int l2    = lane & 15;
    const int brow  = l2 & 7;
    const int bkoff = (l2 >> 3) * 8;

    auto compute_stage = [&](int stg) {
        const uint32_t so = (uint32_t)stg * TILE_BYTES;
#pragma unroll
        for (int ks = 0; ks < 2; ks++) {
            const int k0 = ks * 16;
            uint32_t ah[4][4], al[4][4], bh[4][2], bl[4][2];
#pragma unroll
            for (int mt = 0; mt < 4; mt++) {
                int row = warp_m * 64 + mt * 16 + arow;
                uint32_t off = so + (uint32_t)(row * 80 + (k0 + akoff) * 2);
                ldmat_x4(ah[mt], sbase + AH_OFF + off);
                ldmat_x4(al[mt], sbase + AL_OFF + off);
            }
#pragma unroll
            for (int nt = 0; nt < 4; nt++) {
                int row = warp_n * 32 + nt * 8 + brow;
                uint32_t off = so + (uint32_t)(row * 80 + (k0 + bkoff) * 2);
                ldmat_x2(bh[nt], sbase + BH_OFF + off);
                ldmat_x2(bl[nt], sbase + BL_OFF + off);
            }
#pragma unroll
            for (int mt = 0; mt < 4; mt++)
#pragma unroll
                for (int nt = 0; nt < 4; nt++) {
                    mma_bf16(acc[mt][nt], ah[mt], bh[nt]);
                    mma_bf16(acc[mt][nt], ah[mt], bl[nt]);
                    mma_bf16(acc[mt][nt], al[mt], bh[nt]);
                }
        }
    };

    const int NCHUNK = CC / BK;
    load_stage(0, 0);
    for (int c = 0; c < NCHUNK; c++) {
        if (c + 1 < NCHUNK) {
            load_stage((c + 1) & 1, (c + 1) * BK);
            asm volatile("cp.async.wait_group 1;" ::: "memory");
        } else {
            asm volatile("cp.async.wait_group 0;" ::: "memory");
        }
        __syncthreads();
        compute_stage(c & 1);
        __syncthreads();
    }

    const int gg  = lane >> 2;
    const int tg2 = (lane & 3) * 2;
#pragma unroll
    for (int mt = 0; mt < 4; mt++) {
        int row0 = rowBase + warp_m * 64 + mt * 16 + gg;
#pragma unroll
        for (int nt = 0; nt < 4; nt++) {
            int col = colBase + warp_n * 32 + nt * 8 + tg2;
            float2 bv = *(const float2*)(bias + col);
            float o00 = (acc[mt][nt][0] + bv.x) * scale;
            float o01 = (acc[mt][nt][1] + bv.y) * scale;
            float o10 = (acc[mt][nt][2] + bv.x) * scale;
            float o11 = (acc[mt][nt][3] + bv.y) * scale;
            if (mode == 0) {
                *(float2*)(outf + (size_t)row0 * CC + col) = make_float2(o00, o01);
                *(float2*)(outf + (size_t)(row0 + 8) * CC + col) = make_float2(o10, o11);
            } else if (mode == 1) {
                uint32_t u0 = __float_as_uint(o00), u1 = __float_as_uint(o01);
                uint32_t u2 = __float_as_uint(o10), u3 = __float_as_uint(o11);
                uint16_t* oh16 = (uint16_t*)outh;
                uint16_t* ol16 = (uint16_t*)outl;
                *(uint32_t*)(oh16 + (size_t)row0 * CC + col) = __byte_perm(u0, u1, 0x7632);
                *(uint32_t*)(oh16 + (size_t)(row0 + 8) * CC + col) = __byte_perm(u2, u3, 0x7632);
                *(uint32_t*)(ol16 + (size_t)row0 * CC + col) =
                    pack_bf16x2(o00 - __uint_as_float(u0 & 0xFFFF0000u),
                                o01 - __uint_as_float(u1 & 0xFFFF0000u));
                *(uint32_t*)(ol16 + (size_t)(row0 + 8) * CC + col) =
                    pack_bf16x2(o10 - __uint_as_float(u2 & 0xFFFF0000u),
                                o11 - __uint_as_float(u3 & 0xFFFF0000u));
            } else {
                int hh = col >> 6, d = col & 63;
                int b0 = row0 >> 11, t0 = row0 & 2047;
                size_t base = (((size_t)b0 * HH + hh) * HD + d) * TT + t0;
                uint16_t* oh16 = (uint16_t*)outh;
                __nv_bfloat16* ol16 = outl;
                uint32_t u;
                u = __float_as_uint(o00);
                oh16[base] = (uint16_t)(u >> 16);
                ol16[base] = __float2bfloat16(o00 - __uint_as_float(u & 0xFFFF0000u));
                u = __float_as_uint(o01);
                oh16[base + TT] = (uint16_t)(u >> 16);
                ol16[base + TT] = __float2bfloat16(o01 - __uint_as_float(u & 0xFFFF0000u));
                u = __float_as_uint(o10);
                oh16[base + 8] = (uint16_t)(u >> 16);
                ol16[base + 8] = __float2bfloat16(o10 - __uint_as_float(u & 0xFFFF0000u));
                u = __float_as_uint(o11);
                oh16[base + TT + 8] = (uint16_t)(u >> 16);
                ol16[base + TT + 8] = __float2bfloat16(o11 - __uint_as_float(u & 0xFFFF0000u));
            }
        }
    }
}

// QKV fused: grid.z selects projection (0=Q scaled, 1=K, 2=V transposed)
__global__ __launch_bounds__(256) void gemm_qkv_kernel(
    const __nv_bfloat16* __restrict__ Xh, const __nv_bfloat16* __restrict__ Xl,
    const __nv_bfloat16* __restrict__ Wth, const __nv_bfloat16* __restrict__ Wtl,
    const float* __restrict__ bq, const float* __restrict__ bk, const float* __restrict__ bv,
    __nv_bfloat16* __restrict__ Qh, __nv_bfloat16* __restrict__ Ql,
    __nv_bfloat16* __restrict__ Kh, __nv_bfloat16* __restrict__ Kl,
    __nv_bfloat16* __restrict__ Vth, __nv_bfloat16* __restrict__ Vtl)
{
    extern __shared__ char smem[];
    const int z = blockIdx.z;
    const size_t WSZ = (size_t)CC * CC;
    const __nv_bfloat16* Bh = Wth + (size_t)z * WSZ;
    const __nv_bfloat16* Bl = Wtl + (size_t)z * WSZ;
    const float* bias = (z == 0) ? bq : (z == 1) ? bk : bv;
    __nv_bfloat16* oh = (z == 0) ? Qh : (z == 1) ? Kh : Vth;
    __nv_bfloat16* ol = (z == 0) ? Ql : (z == 1) ? Kl : Vtl;
    int mode = (z == 2) ? 2 : 1;
    float scale = (z == 0) ? SCALE_Q : 1.0f;
    gemm_core(Xh, Xl, Bh, Bl, bias, nullptr, oh, ol, mode, scale, smem);
}

// Output projection: fp32 out
__global__ __launch_bounds__(256) void gemm_proj_kernel(
    const __nv_bfloat16* __restrict__ Ah, const __nv_bfloat16* __restrict__ Al,
    const __nv_bfloat16* __restrict__ Bh, const __nv_bfloat16* __restrict__ Bl,
    const float* __restrict__ bias, float* __restrict__ outf)
{
    extern __shared__ char smem[];
    gemm_core(Ah, Al, Bh, Bl, bias, outf, nullptr, nullptr, 0, 1.0f, smem);
}

// ---------------------------------------------------------------------------
// Tensor-core causal flash attention: R11 compute structure (per-kc fragment
// build) + double-buffered KV stages (sole change this round).
// CTA: 128 q-rows, 4 warps (32 rows each). KV blocks of 64.
// ---------------------------------------------------------------------------
#define APITCH 144            // 72 bf16 per row (bytes)
#define SQH 0
#define SQL 18432
#define KVBASE 36864
#define KVSTG 36864           // per stage: KH +0 / KL +9216 / VH +18432 / VL +27648
#define ATTN_SMEM (KVBASE + 2 * KVSTG)   // 110592

__global__ __launch_bounds__(128) void attn_mma_kernel(
    const __nv_bfloat16* __restrict__ Qh_, const __nv_bfloat16* __restrict__ Ql_,
    const __nv_bfloat16* __restrict__ Kh_, const __nv_bfloat16* __restrict__ Kl_,
    const __nv_bfloat16* __restrict__ Vh_, const __nv_bfloat16* __restrict__ Vl_)
{
    extern __shared__ char smem[];
    const uint32_t sb = smem_u32(smem);
    const int tid = threadIdx.x, lane = tid & 31, wid = tid >> 5;
    const int qb = gridDim.x - 1 - blockIdx.x;   // heavy blocks first
    const int h  = blockIdx.y, b = blockIdx.z;

    // Q tile: 128 rows x 64 bf16, hi/lo (cp.async group 0)
#pragma unroll
    for (int i = 0; i < 8; i++) {
        int v = tid + i * 128, r = v >> 3, c = v & 7;
        uint32_t so = (uint32_t)(r * APITCH + c * 16);
        size_t g = ((size_t)b * TT + qb * 128 + r) * CC + h * HD + c * 8;
        cp_async16(sb + SQH + so, Qh_ + g);
        cp_async16(sb + SQL + so, Ql_ + g);
    }
    CP_COMMIT();

    auto load_kv = [&](int stg, int kb) {
        const uint32_t kvb = sb + KVBASE + (uint32_t)stg * KVSTG;
#pragma unroll
        for (int i = 0; i < 4; i++) {
            int v = tid + i * 128, r = v >> 3, c = v & 7;
            uint32_t so = (uint32_t)(r * APITCH + c * 16);
            size_t gk = ((size_t)b * TT + kb * 64 + r) * CC + h * HD + c * 8;
            cp_async16(kvb +         so, Kh_ + gk);
            cp_async16(kvb +  9216 + so, Kl_ + gk);
            size_t gv = (((size_t)b * HH + h) * HD + r) * TT + kb * 64 + c * 8;
            cp_async16(kvb + 18432 + so, Vh_ + gv);
            cp_async16(kvb + 27648 + so, Vl_ + gv);
        }
        CP_COMMIT();
    };

    const int g4 = lane >> 2, t4 = lane & 3;
    const int arow  = (lane & 7) + ((lane >> 3) & 1) * 8;
    const int akoff = (lane >> 4) * 8;
    const int l2 = lane & 15, brow = l2 & 7, bkoff = (l2 >> 3) * 8;
    const int r0w = qb * 128 + wid * 32;   // this warp's first q row

    float O[2][8][4];
#pragma unroll
    for (int mt = 0; mt < 2; mt++)
#pragma unroll
        for (int nt = 0; nt < 8; nt++)
#pragma unroll
            for (int r = 0; r < 4; r++) O[mt][nt][r] = 0.f;
    float mr[2][2] = {{-1e30f, -1e30f}, {-1e30f, -1e30f}};
    float lr[2][2] = {{0.f, 0.f}, {0.f, 0.f}};

    const int nkv = qb * 2 + 2;
    load_kv(0, 0);

    for (int kb = 0; kb < nkv; kb++) {
        const int p = kb & 1;
        if (kb + 1 < nkv) {
            load_kv(p ^ 1, kb + 1);
            asm volatile("cp.async.wait_group 1;" ::: "memory");
        } else {
            asm volatile("cp.async.wait_group 0;" ::: "memory");
        }
        __syncthreads();

        // warp-level skip: block entirely above this warp's rows -> all masked
        if (kb * 64 <= r0w + 31) {

        const uint32_t kvb = sb + KVBASE + (uint32_t)p * KVSTG;

        // ---- S = Q K^T ----
        float S[2][8][4];
#pragma unroll
        for (int mt = 0; mt < 2; mt++)
#pragma unroll
            for (int nt = 0; nt < 8; nt++)
#pragma unroll
                for (int r = 0; r < 4; r++) S[mt][nt][r] = 0.f;
#pragma unroll
        for (int kc = 0; kc < 4; kc++) {
            uint32_t ah[2][4], al[2][4], bh2[8][2], bl2[8][2];
#pragma unroll
            for (int mt = 0; mt < 2; mt++) {
                int row = wid * 32 + mt * 16 + arow;
                uint32_t off = (uint32_t)(row * APITCH + (kc * 16 + akoff) * 2);
                ldmat_x4(ah[mt], sb + SQH + off);
                ldmat_x4(al[mt], sb + SQL + off);
            }
#pragma unroll
            for (int nt = 0; nt < 8; nt++) {
                int row = nt * 8 + brow;
                uint32_t off = (uint32_t)(row * APITCH + (kc * 16 + bkoff) * 2);
                ldmat_x2(bh2[nt], kvb + off);
                ldmat_x2(bl2[nt], kvb + 9216 + off);
            }
#pragma unroll
            for (int mt = 0; mt < 2; mt++)
#pragma unroll
                for (int nt = 0; nt < 8; nt++) {
                    mma_bf16(S[mt][nt], ah[mt], bh2[nt]);
                    mma_bf16(S[mt][nt], ah[mt], bl2[nt]);
                    mma_bf16(S[mt][nt], al[mt], bh2[nt]);
                }
        }

        // ---- causal mask (diagonal-region blocks only) ----
        if (kb * 64 + 63 > r0w) {
#pragma unroll
            for (int mt = 0; mt < 2; mt++) {
                int r0 = r0w + mt * 16 + g4;
#pragma unroll
                for (int nt = 0; nt < 8; nt++) {
                    int k0 = kb * 64 + nt * 8 + 2 * t4;
                    if (k0     > r0)     S[mt][nt][0] = -1e30f;
                    if (k0 + 1 > r0)     S[mt][nt][1] = -1e30f;
                    if (k0     > r0 + 8) S[mt][nt][2] = -1e30f;
                    if (k0 + 1 > r0 + 8) S[mt][nt][3] = -1e30f;
                }
            }
        }

        // ---- online softmax ----
#pragma unroll
        for (int mt = 0; mt < 2; mt++) {
#pragma unroll
            for (int rh = 0; rh < 2; rh++) {
                float mx = -1e30f;
#pragma unroll
                for (int nt = 0; nt < 8; nt++)
                    mx = fmaxf(mx, fmaxf(S[mt][nt][rh * 2], S[mt][nt][rh * 2 + 1]));
                mx = fmaxf(mx, __shfl_xor_sync(0xffffffffu, mx, 1));
                mx = fmaxf(mx, __shfl_xor_sync(0xffffffffu, mx, 2));
                float mnew = fmaxf(mr[mt][rh], mx);
                float corr = ex2f(mr[mt][rh] - mnew);
                mr[mt][rh] = mnew;
                float sum = 0.f;
#pragma unroll
                for (int nt = 0; nt < 8; nt++) {
                    float p0 = ex2f(S[mt][nt][rh * 2]     - mnew);
                    float p1 = ex2f(S[mt][nt][rh * 2 + 1] - mnew);
                    S[mt][nt][rh * 2] = p0; S[mt][nt][rh * 2 + 1] = p1;
                    sum += p0 + p1;
                }
                sum += __shfl_xor_sync(0xffffffffu, sum, 1);
                sum += __shfl_xor_sync(0xffffffffu, sum, 2);
                lr[mt][rh] = lr[mt][rh] * corr + sum;
#pragma unroll
                for (int nt = 0; nt < 8; nt++) {
                    O[mt][nt][rh * 2]     *= corr;
                    O[mt][nt][rh * 2 + 1] *= corr;
                }
            }
        }

        // ---- O += P V (per-kc fragment build; R11 structure) ----
#pragma unroll
        for (int kc = 0; kc < 4; kc++) {
            uint32_t ph[2][4], pl[2][4];
#pragma unroll
            for (int mt = 0; mt < 2; mt++)
#pragma unroll
                for (int half = 0; half < 2; half++) {
                    int nt = 2 * kc + half;
                    uint32_t u0 = __float_as_uint(S[mt][nt][0]);
                    uint32_t u1 = __float_as_uint(S[mt][nt][1]);
                    uint32_t u2 = __float_as_uint(S[mt][nt][2]);
                    uint32_t u3 = __float_as_uint(S[mt][nt][3]);
                    ph[mt][half * 2 + 0] = __byte_perm(u0, u1, 0x7632);
                    ph[mt][half * 2 + 1] = __byte_perm(u2, u3, 0x7632);
                    float q0 = S[mt][nt][0] - __uint_as_float(u0 & 0xFFFF0000u);
                    float q1 = S[mt][nt][1] - __uint_as_float(u1 & 0xFFFF0000u);
                    float q2 = S[mt][nt][2] - __uint_as_float(u2 & 0xFFFF0000u);
                    float q3 = S[mt][nt][3] - __uint_as_float(u3 & 0xFFFF0000u);
                    pl[mt][half * 2 + 0] = pack_bf16x2(q0, q1);
                    pl[mt][half * 2 + 1] = pack_bf16x2(q2, q3);
                }
            uint32_t vh2[2], vl2[2];
#pragma unroll
            for (int nt = 0; nt < 8; nt++) {
                int row = nt * 8 + brow;
                uint32_t off = (uint32_t)(row * APITCH + (kc * 16 + bkoff) * 2);
                ldmat_x2(vh2, kvb + 18432 + off);
                ldmat_x2(vl2, kvb + 27648 + off);
#pragma unroll
                for (int mt = 0; mt < 2; mt++) {
                    mma_bf16(O[mt][nt], ph[mt], vh2);
                    mma_bf16(O[mt][nt], pl[mt], vh2);
                    mma_bf16(O[mt][nt], ph[mt], vl2);
                }
            }
        }

        }  // warp-level skip

        __syncthreads();   // all warps done with stage p before it is reloaded
    }

    // ---- normalize + write trunc-split Y ----
#pragma unroll
    for (int mt = 0; mt < 2; mt++) {
        float i0 = 1.f / lr[mt][0];
        float i1 = 1.f / lr[mt][1];
        int r0 = qb * 128 + wid * 32 + mt * 16 + g4;
#pragma unroll
        for (int nt = 0; nt < 8; nt++) {
            int col = h * HD + nt * 8 + 2 * t4;
            float f0 = O[mt][nt][0] * i0, f1 = O[mt][nt][1] * i0;
            uint32_t u0 = __float_as_uint(f0), u1 = __float_as_uint(f1);
            size_t off0 = ((size_t)b * TT + r0) * CC + col;
            *(uint32_t*)((uint16_t*)g_Yh + off0) = __byte_perm(u0, u1, 0x7632);
            *(uint32_t*)((uint16_t*)g_Yl + off0) =
                pack_bf16x2(f0 - __uint_as_float(u0 & 0xFFFF0000u),
                            f1 - __uint_as_float(u1 & 0xFFFF0000u));
            float f2 = O[mt][nt][2] * i1, f3 = O[mt][nt][3] * i1;
            uint32_t u2 = __float_as_uint(f2), u3 = __float_as_uint(f3);
            size_t off1 = ((size_t)b * TT + r0 + 8) * CC + col;
            *(uint32_t*)((uint16_t*)g_Yh + off1) = __byte_perm(u2, u3, 0x7632);
            *(uint32_t*)((uint16_t*)g_Yl + off1) =
                pack_bf16x2(f2 - __uint_as_float(u2 & 0xFFFF0000u),
                            f3 - __uint_as_float(u3 & 0xFFFF0000u));
        }
    }
}

// ---------------------------------------------------------------------------
extern "C" void kernel_launch(void* const* d_in, const int* in_sizes, int n_in,
                              void* d_out, int out_size)
{
    const float* x  = (const float*)d_in[0];
    const float* Wq = (const float*)d_in[1];
    const float* bq = (const float*)d_in[2];
    const float* Wk = (const float*)d_in[3];
    const float* bk = (const float*)d_in[4];
    const float* Wv = (const float*)d_in[5];
    const float* bv = (const float*)d_in[6];
    const float* Wp = (const float*)d_in[7];
    const float* bp = (const float*)d_in[8];
    float* out = (float*)d_out;

    __nv_bfloat16 *Xh, *Xl, *Qh, *Ql, *Kh, *Kl, *Vth, *Vtl, *Yh, *Yl, *Wth, *Wtl;
    cudaGetSymbolAddress((void**)&Xh,  g_Xh);
    cudaGetSymbolAddress((void**)&Xl,  g_Xl);
    cudaGetSymbolAddress((void**)&Qh,  g_Qh);
    cudaGetSymbolAddress((void**)&Ql,  g_Ql);
    cudaGetSymbolAddress((void**)&Kh,  g_Kh);
    cudaGetSymbolAddress((void**)&Kl,  g_Kl);
    cudaGetSymbolAddress((void**)&Vth, g_Vth);
    cudaGetSymbolAddress((void**)&Vtl, g_Vtl);
    cudaGetSymbolAddress((void**)&Yh,  g_Yh);
    cudaGetSymbolAddress((void**)&Yl,  g_Yl);
    cudaGetSymbolAddress((void**)&Wth, g_Wth);
    cudaGetSymbolAddress((void**)&Wtl, g_Wtl);

    cudaFuncSetAttribute(gemm_qkv_kernel,
                         cudaFuncAttributeMaxDynamicSharedMemorySize, GEMM_SMEM);
    cudaFuncSetAttribute(gemm_proj_kernel,
                         cudaFuncAttributeMaxDynamicSharedMemorySize, GEMM_SMEM);
    cudaFuncSetAttribute(attn_mma_kernel,
                         cudaFuncAttributeMaxDynamicSharedMemorySize, ATTN_SMEM);

    const size_t WSZ = (size_t)CC * CC;

    // 1) split x into bf16 hi/lo
    convert_split_kernel<<<1024, 256>>>(x, Xh, Xl, MM * CC / 4);

    // 2) transpose+split the 4 weights (one launch, grid.z = 4)
    dim3 tgrd(CC / 32, CC / 32, 4), tblk(32, 8);
    transpose_split_kernel<<<tgrd, tblk>>>(Wq, Wk, Wv, Wp, Wth, Wtl);

    // 3) fused Q/K/V projections (one launch, grid.z = 3)
    dim3 qkvgrd(CC / 128, MM / 128, 3);
    gemm_qkv_kernel<<<qkvgrd, 256, GEMM_SMEM>>>(Xh, Xl, Wth, Wtl, bq, bk, bv,
                                                Qh, Ql, Kh, Kl, Vth, Vtl);

    // 4) tensor-core flash attention (double-buffered KV)
    dim3 agrd(TT / 128, HH, BB);
    attn_mma_kernel<<<agrd, 128, ATTN_SMEM>>>(Qh, Ql, Kh, Kl, Vth, Vtl);

    // 5) output projection (fp32 out)
    dim3 ggrd(CC / 128, MM / 128);
    gemm_proj_kernel<<<ggrd, 256, GEMM_SMEM>>>(Yh, Yl, Wth + 3*WSZ, Wtl + 3*WSZ, bp, out);

    (void)in_sizes; (void)n_in; (void)out_size;
}

// round 13
// speedup vs baseline: 1.0088x; 1.0088x over previous
#include <cuda_runtime.h>
#include <cuda_bf16.h>
#include <cstdint>

// Problem constants
#define BB 2
#define TT 2048
#define CC 1024
#define HH 16
#define HD 64
#define MM (BB*TT)   // 4096 rows

// 0.125 (1/sqrt(64)) * log2(e), folded into Q projection
#define SCALE_Q 0.18033688f

// ---------------------------------------------------------------------------
// Scratch (__device__ globals: allocation-free rule)
// ---------------------------------------------------------------------------
__device__ __nv_bfloat16 g_Xh[(size_t)MM*CC];
__device__ __nv_bfloat16 g_Xl[(size_t)MM*CC];
__device__ __nv_bfloat16 g_Qh[(size_t)MM*CC];
__device__ __nv_bfloat16 g_Ql[(size_t)MM*CC];
__device__ __nv_bfloat16 g_Kh[(size_t)MM*CC];
__device__ __nv_bfloat16 g_Kl[(size_t)MM*CC];
__device__ __nv_bfloat16 g_Vth[(size_t)MM*CC];  // V transposed per head [b,h,d,t]
__device__ __nv_bfloat16 g_Vtl[(size_t)MM*CC];
__device__ __nv_bfloat16 g_Yh[(size_t)MM*CC];
__device__ __nv_bfloat16 g_Yl[(size_t)MM*CC];
__device__ __nv_bfloat16 g_Wth[(size_t)4*CC*CC];
__device__ __nv_bfloat16 g_Wtl[(size_t)4*CC*CC];

// ---------------------------------------------------------------------------
// PTX helpers
// ---------------------------------------------------------------------------
__device__ __forceinline__ uint32_t smem_u32(const void* p) {
    uint32_t a;
    asm("{ .reg .u64 t; cvta.to.shared.u64 t, %1; cvt.u32.u64 %0, t; }" : "=r"(a) : "l"(p));
    return a;
}
__device__ __forceinline__ void cp_async16(uint32_t saddr, const void* gaddr) {
    asm volatile("cp.async.ca.shared.global [%0], [%1], 16;" :: "r"(saddr), "l"(gaddr));
}
#define CP_COMMIT() asm volatile("cp.async.commit_group;" ::: "memory")

__device__ __forceinline__ void ldmat_x4(uint32_t* r, uint32_t addr) {
    asm volatile("ldmatrix.sync.aligned.m8n8.x4.shared.b16 {%0,%1,%2,%3}, [%4];"
        : "=r"(r[0]), "=r"(r[1]), "=r"(r[2]), "=r"(r[3]) : "r"(addr));
}
__device__ __forceinline__ void ldmat_x2(uint32_t* r, uint32_t addr) {
    asm volatile("ldmatrix.sync.aligned.m8n8.x2.shared.b16 {%0,%1}, [%2];"
        : "=r"(r[0]), "=r"(r[1]) : "r"(addr));
}
__device__ __forceinline__ void mma_bf16(float* c, const uint32_t* a, const uint32_t* b) {
    asm volatile("mma.sync.aligned.m16n8k16.row.col.f32.bf16.bf16.f32 "
        "{%0,%1,%2,%3}, {%4,%5,%6,%7}, {%8,%9}, {%0,%1,%2,%3};"
        : "+f"(c[0]), "+f"(c[1]), "+f"(c[2]), "+f"(c[3])
        : "r"(a[0]), "r"(a[1]), "r"(a[2]), "r"(a[3]), "r"(b[0]), "r"(b[1]));
}
__device__ __forceinline__ uint32_t pack_bf16x2(float lo, float hi) {
    uint32_t d;
    asm("cvt.rn.satfinite.bf16x2.f32 %0, %1, %2;" : "=r"(d) : "f"(hi), "f"(lo));
    return d;
}
__device__ __forceinline__ float ex2f(float x) {
    float y; asm("ex2.approx.f32 %0, %1;" : "=f"(y) : "f"(x)); return y;
}

// ---------------------------------------------------------------------------
// Split-precision conversion kernels
// ---------------------------------------------------------------------------
__device__ __forceinline__ void split_bf16(float v, __nv_bfloat16& h, __nv_bfloat16& l) {
    h = __float2bfloat16(v);
    l = __float2bfloat16(v - __bfloat162float(h));
}

__global__ void convert_split_kernel(const float* __restrict__ in,
                                     __nv_bfloat16* __restrict__ oh,
                                     __nv_bfloat16* __restrict__ ol, int n4)
{
    for (int i = blockIdx.x * blockDim.x + threadIdx.x; i < n4; i += gridDim.x * blockDim.x) {
        float4 v = ((const float4*)in)[i];
        __nv_bfloat16 h0,l0,h1,l1,h2,l2,h3,l3;
        split_bf16(v.x,h0,l0); split_bf16(v.y,h1,l1);
        split_bf16(v.z,h2,l2); split_bf16(v.w,h3,l3);
        ((__nv_bfloat162*)oh)[2*i]   = __halves2bfloat162(h0,h1);
        ((__nv_bfloat162*)oh)[2*i+1] = __halves2bfloat162(h2,h3);
        ((__nv_bfloat162*)ol)[2*i]   = __halves2bfloat162(l0,l1);
        ((__nv_bfloat162*)ol)[2*i+1] = __halves2bfloat162(l2,l3);
    }
}

// 4 weights W[K,N] -> Wt[N,K] split into hi/lo bf16; grid.z selects weight
__global__ void transpose_split_kernel(
    const float* __restrict__ W0, const float* __restrict__ W1,
    const float* __restrict__ W2, const float* __restrict__ W3,
    __nv_bfloat16* __restrict__ Th, __nv_bfloat16* __restrict__ Tl)
{
    __shared__ float t[32][33];
    const int z = blockIdx.z;
    const float* W = (z == 0) ? W0 : (z == 1) ? W1 : (z == 2) ? W2 : W3;
    __nv_bfloat16* Thz = Th + (size_t)z * CC * CC;
    __nv_bfloat16* Tlz = Tl + (size_t)z * CC * CC;
    int xi = blockIdx.x * 32 + threadIdx.x;
    int yi = blockIdx.y * 32 + threadIdx.y;
#pragma unroll
    for (int j = 0; j < 32; j += 8)
        t[threadIdx.y + j][threadIdx.x] = W[(size_t)(yi + j) * CC + xi];
    __syncthreads();
    int xo = blockIdx.y * 32 + threadIdx.x;
    int yo = blockIdx.x * 32 + threadIdx.y;
#pragma unroll
    for (int j = 0; j < 32; j += 8) {
        float v = t[threadIdx.x][threadIdx.y + j];
        __nv_bfloat16 h, l;
        split_bf16(v, h, l);
        Thz[(size_t)(yo + j) * CC + xo] = h;
        Tlz[(size_t)(yo + j) * CC + xo] = l;
    }
}

// ---------------------------------------------------------------------------
// GEMM core (device function): [4096,1024] = A @ Wt^T + bias, epilogue mode:
//   mode 0: fp32 row-major; mode 1: split bf16 row-major; mode 2: split + V-transpose
// ---------------------------------------------------------------------------
#define BK 32
#define PITCH 40
#define TILE_BYTES (128 * PITCH * 2)
#define AH_OFF 0
#define AL_OFF (2 * TILE_BYTES)
#define BH_OFF (4 * TILE_BYTES)
#define BL_OFF (6 * TILE_BYTES)
#define GEMM_SMEM (8 * TILE_BYTES)     // 81920 B

__device__ __forceinline__ void gemm_core(
    const __nv_bfloat16* __restrict__ Ah, const __nv_bfloat16* __restrict__ Al,
    const __nv_bfloat16* __restrict__ Bh, const __nv_bfloat16* __restrict__ Bl,
    const float* __restrict__ bias,
    float* __restrict__ outf,
    __nv_bfloat16* __restrict__ outh, __nv_bfloat16* __restrict__ outl,
    int mode, float scale, char* smem)
{
    const uint32_t sbase = smem_u32(smem);
    const int tid  = threadIdx.x;
    const int lane = tid & 31;
    const int wid  = tid >> 5;
    const int warp_m = wid >> 2;
    const int warp_n = wid & 3;

    const int rowBase = blockIdx.y * 128;
    const int colBase = blockIdx.x * 128;

    float acc[4][4][4];
#pragma unroll
    for (int i = 0; i < 4; i++)
#pragma unroll
        for (int j = 0; j < 4; j++)
#pragma unroll
            for (int r = 0; r < 4; r++) acc[i][j][r] = 0.f;

    auto load_stage = [&](int stg, int kc0) {
        const uint32_t so = (uint32_t)stg * TILE_BYTES;
#pragma unroll
        for (int it = 0; it < 2; it++) {
            int v = tid + it * 256;
            int r = v >> 2;
            int cv = v & 3;
            uint32_t doff = so + (uint32_t)(r * 80 + cv * 16);
            size_t gA = (size_t)(rowBase + r) * CC + kc0 + cv * 8;
            size_t gB = (size_t)(colBase + r) * CC + kc0 + cv * 8;
            cp_async16(sbase + AH_OFF + doff, Ah + gA);
            cp_async16(sbase + AL_OFF + doff, Al + gA);
            cp_async16(sbase + BH_OFF + doff, Bh + gB);
            cp_async16(sbase + BL_OFF + doff, Bl + gB);
        }
        CP_COMMIT();
    };

    const int arow  = (lane & 7) + ((lane >> 3) & 1) * 8;
    const int akoff = (lane >> 4) * 8;
    const int l2    = lane & 15;
    const int brow  = l2 & 7;
    const int bkoff = (l2 >> 3) * 8;

    auto compute_stage = [&](int stg) {
        const uint32_t so = (uint32_t)stg * TILE_BYTES;
#pragma unroll
        for (int ks = 0; ks < 2; ks++) {
            const int k0 = ks * 16;
            uint32_t ah[4][4], al[4][4], bh[4][2], bl[4][2];
#pragma unroll
            for (int mt = 0; mt < 4; mt++) {
                int row = warp_m * 64 + mt * 16 + arow;
                uint32_t off = so + (uint32_t)(row * 80 + (k0 + akoff) * 2);
                ldmat_x4(ah[mt], sbase + AH_OFF + off);
                ldmat_x4(al[mt], sbase + AL_OFF + off);
            }
#pragma unroll
            for (int nt = 0; nt < 4; nt++) {
                int row = warp_n * 32 + nt * 8 + brow;
                uint32_t off = so + (uint32_t)(row * 80 + (k0 + bkoff) * 2);
                ldmat_x2(bh[nt], sbase + BH_OFF + off);
                ldmat_x2(bl[nt], sbase + BL_OFF + off);
            }
#pragma unroll
            for (int mt = 0; mt < 4; mt++)
#pragma unroll
                for (int nt = 0; nt < 4; nt++) {
                    mma_bf16(acc[mt][nt], ah[mt], bh[nt]);
                    mma_bf16(acc[mt][nt], ah[mt], bl[nt]);
                    mma_bf16(acc[mt][nt], al[mt], bh[nt]);
                }
        }
    };

    const int NCHUNK = CC / BK;
    load_stage(0, 0);
    for (int c = 0; c < NCHUNK; c++) {
        if (c + 1 < NCHUNK) {
            load_stage((c + 1) & 1, (c + 1) * BK);
            asm volatile("cp.async.wait_group 1;" ::: "memory");
        } else {
            asm volatile("cp.async.wait_group 0;" ::: "memory");
        }
        __syncthreads();
        compute_stage(c & 1);
        __syncthreads();
    }

    const int gg  = lane >> 2;
    const int tg2 = (lane & 3) * 2;
#pragma unroll
    for (int mt = 0; mt < 4; mt++) {
        int row0 = rowBase + warp_m * 64 + mt * 16 + gg;
#pragma unroll
        for (int nt = 0; nt < 4; nt++) {
            int col = colBase + warp_n * 32 + nt * 8 + tg2;
            float2 bv = *(const float2*)(bias + col);
            float o00 = (acc[mt][nt][0] + bv.x) * scale;
            float o01 = (acc[mt][nt][1] + bv.y) * scale;
            float o10 = (acc[mt][nt][2] + bv.x) * scale;
            float o11 = (acc[mt][nt][3] + bv.y) * scale;
            if (mode == 0) {
                *(float2*)(outf + (size_t)row0 * CC + col) = make_float2(o00, o01);
                *(float2*)(outf + (size_t)(row0 + 8) * CC + col) = make_float2(o10, o11);
            } else if (mode == 1) {
                uint32_t u0 = __float_as_uint(o00), u1 = __float_as_uint(o01);
                uint32_t u2 = __float_as_uint(o10), u3 = __float_as_uint(o11);
                uint16_t* oh16 = (uint16_t*)outh;
                uint16_t* ol16 = (uint16_t*)outl;
                *(uint32_t*)(oh16 + (size_t)row0 * CC + col) = __byte_perm(u0, u1, 0x7632);
                *(uint32_t*)(oh16 + (size_t)(row0 + 8) * CC + col) = __byte_perm(u2, u3, 0x7632);
                *(uint32_t*)(ol16 + (size_t)row0 * CC + col) =
                    pack_bf16x2(o00 - __uint_as_float(u0 & 0xFFFF0000u),
                                o01 - __uint_as_float(u1 & 0xFFFF0000u));
                *(uint32_t*)(ol16 + (size_t)(row0 + 8) * CC + col) =
                    pack_bf16x2(o10 - __uint_as_float(u2 & 0xFFFF0000u),
                                o11 - __uint_as_float(u3 & 0xFFFF0000u));
            } else {
                int hh = col >> 6, d = col & 63;
                int b0 = row0 >> 11, t0 = row0 & 2047;
                size_t base = (((size_t)b0 * HH + hh) * HD + d) * TT + t0;
                uint16_t* oh16 = (uint16_t*)outh;
                __nv_bfloat16* ol16 = outl;
                uint32_t u;
                u = __float_as_uint(o00);
                oh16[base] = (uint16_t)(u >> 16);
                ol16[base] = __float2bfloat16(o00 - __uint_as_float(u & 0xFFFF0000u));
                u = __float_as_uint(o01);
                oh16[base + TT] = (uint16_t)(u >> 16);
                ol16[base + TT] = __float2bfloat16(o01 - __uint_as_float(u & 0xFFFF0000u));
                u = __float_as_uint(o10);
                oh16[base + 8] = (uint16_t)(u >> 16);
                ol16[base + 8] = __float2bfloat16(o10 - __uint_as_float(u & 0xFFFF0000u));
                u = __float_as_uint(o11);
                oh16[base + TT + 8] = (uint16_t)(u >> 16);
                ol16[base + TT + 8] = __float2bfloat16(o11 - __uint_as_float(u & 0xFFFF0000u));
            }
        }
    }
}

// QKV fused: grid.z selects projection (0=Q scaled, 1=K, 2=V transposed)
__global__ __launch_bounds__(256) void gemm_qkv_kernel(
    const __nv_bfloat16* __restrict__ Xh, const __nv_bfloat16* __restrict__ Xl,
    const __nv_bfloat16* __restrict__ Wth, const __nv_bfloat16* __restrict__ Wtl,
    const float* __restrict__ bq, const float* __restrict__ bk, const float* __restrict__ bv,
    __nv_bfloat16* __restrict__ Qh, __nv_bfloat16* __restrict__ Ql,
    __nv_bfloat16* __restrict__ Kh, __nv_bfloat16* __restrict__ Kl,
    __nv_bfloat16* __restrict__ Vth, __nv_bfloat16* __restrict__ Vtl)
{
    extern __shared__ char smem[];
    const int z = blockIdx.z;
    const size_t WSZ = (size_t)CC * CC;
    const __nv_bfloat16* Bh = Wth + (size_t)z * WSZ;
    const __nv_bfloat16* Bl = Wtl + (size_t)z * WSZ;
    const float* bias = (z == 0) ? bq : (z == 1) ? bk : bv;
    __nv_bfloat16* oh = (z == 0) ? Qh : (z == 1) ? Kh : Vth;
    __nv_bfloat16* ol = (z == 0) ? Ql : (z == 1) ? Kl : Vtl;
    int mode = (z == 2) ? 2 : 1;
    float scale = (z == 0) ? SCALE_Q : 1.0f;
    gemm_core(Xh, Xl, Bh, Bl, bias, nullptr, oh, ol, mode, scale, smem);
}

// Output projection: fp32 out
__global__ __launch_bounds__(256) void gemm_proj_kernel(
    const __nv_bfloat16* __restrict__ Ah, const __nv_bfloat16* __restrict__ Al,
    const __nv_bfloat16* __restrict__ Bh, const __nv_bfloat16* __restrict__ Bl,
    const float* __restrict__ bias, float* __restrict__ outf)
{
    extern __shared__ char smem[];
    gemm_core(Ah, Al, Bh, Bl, bias, outf, nullptr, nullptr, 0, 1.0f, smem);
}

// ---------------------------------------------------------------------------
// Tensor-core causal flash attention.
// R13: 256 threads, 8 warps x 16 q-rows (mt dimension removed -> S/O arrays
// halved -> target <=128 regs for 2 CTAs/SM). Single-buffered KV (R11 proven).
// ---------------------------------------------------------------------------
#define APITCH 144            // 72 bf16 per row (bytes)
#define SQH 0
#define SQL 18432
#define SKH 36864
#define SKL 46080
#define SVH 55296
#define SVL 64512
#define ATTN_SMEM 73728

__global__ __launch_bounds__(256, 2) void attn_mma_kernel(
    const __nv_bfloat16* __restrict__ Qh_, const __nv_bfloat16* __restrict__ Ql_,
    const __nv_bfloat16* __restrict__ Kh_, const __nv_bfloat16* __restrict__ Kl_,
    const __nv_bfloat16* __restrict__ Vh_, const __nv_bfloat16* __restrict__ Vl_)
{
    extern __shared__ char smem[];
    const uint32_t sb = smem_u32(smem);
    const int tid = threadIdx.x, lane = tid & 31, wid = tid >> 5;
    const int qb = gridDim.x - 1 - blockIdx.x;   // heavy blocks first
    const int h  = blockIdx.y, b = blockIdx.z;

    // Q tile: 128 rows x 64 bf16, hi/lo
#pragma unroll
    for (int i = 0; i < 4; i++) {
        int v = tid + i * 256, r = v >> 3, c = v & 7;
        uint32_t so = (uint32_t)(r * APITCH + c * 16);
        size_t g = ((size_t)b * TT + qb * 128 + r) * CC + h * HD + c * 8;
        cp_async16(sb + SQH + so, Qh_ + g);
        cp_async16(sb + SQL + so, Ql_ + g);
    }
    CP_COMMIT();

    const int g4 = lane >> 2, t4 = lane & 3;
    const int arow  = (lane & 7) + ((lane >> 3) & 1) * 8;
    const int akoff = (lane >> 4) * 8;
    const int l2 = lane & 15, brow = l2 & 7, bkoff = (l2 >> 3) * 8;
    const int r0w = qb * 128 + wid * 16;   // this warp's first q row (16-row slice)

    float O[8][4];
#pragma unroll
    for (int nt = 0; nt < 8; nt++)
#pragma unroll
        for (int r = 0; r < 4; r++) O[nt][r] = 0.f;
    float mr[2] = {-1e30f, -1e30f};
    float lr[2] = {0.f, 0.f};

    const int nkv = qb * 2 + 2;
    for (int kb = 0; kb < nkv; kb++) {
        // K tile [64 keys][64 hd], Vt tile [64 hd][64 keys], hi/lo
#pragma unroll
        for (int i = 0; i < 2; i++) {
            int v = tid + i * 256, r = v >> 3, c = v & 7;
            uint32_t so = (uint32_t)(r * APITCH + c * 16);
            size_t gk = ((size_t)b * TT + kb * 64 + r) * CC + h * HD + c * 8;
            cp_async16(sb + SKH + so, Kh_ + gk);
            cp_async16(sb + SKL + so, Kl_ + gk);
            size_t gv = (((size_t)b * HH + h) * HD + r) * TT + kb * 64 + c * 8;
            cp_async16(sb + SVH + so, Vh_ + gv);
            cp_async16(sb + SVL + so, Vl_ + gv);
        }
        CP_COMMIT();
        asm volatile("cp.async.wait_group 0;" ::: "memory");
        __syncthreads();

        // warp-level skip: block entirely above this warp's 16 rows
        if (kb * 64 <= r0w + 15) {

        // ---- S = Q K^T ----
        float S[8][4];
#pragma unroll
        for (int nt = 0; nt < 8; nt++)
#pragma unroll
            for (int r = 0; r < 4; r++) S[nt][r] = 0.f;
#pragma unroll
        for (int kc = 0; kc < 4; kc++) {
            uint32_t ah[4], al[4], bh2[8][2], bl2[8][2];
            {
                int row = wid * 16 + arow;
                uint32_t off = (uint32_t)(row * APITCH + (kc * 16 + akoff) * 2);
                ldmat_x4(ah, sb + SQH + off);
                ldmat_x4(al, sb + SQL + off);
            }
#pragma unroll
            for (int nt = 0; nt < 8; nt++) {
                int row = nt * 8 + brow;
                uint32_t off = (uint32_t)(row * APITCH + (kc * 16 + bkoff) * 2);
                ldmat_x2(bh2[nt], sb + SKH + off);
                ldmat_x2(bl2[nt], sb + SKL + off);
            }
#pragma unroll
            for (int nt = 0; nt < 8; nt++) {
                mma_bf16(S[nt], ah, bh2[nt]);
                mma_bf16(S[nt], ah, bl2[nt]);
                mma_bf16(S[nt], al, bh2[nt]);
            }
        }

        // ---- causal mask (diagonal-region blocks only) ----
        if (kb * 64 + 63 > r0w) {
            int r0 = r0w + g4;
#pragma unroll
            for (int nt = 0; nt < 8; nt++) {
                int k0 = kb * 64 + nt * 8 + 2 * t4;
                if (k0     > r0)     S[nt][0] = -1e30f;
                if (k0 + 1 > r0)     S[nt][1] = -1e30f;
                if (k0     > r0 + 8) S[nt][2] = -1e30f;
                if (k0 + 1 > r0 + 8) S[nt][3] = -1e30f;
            }
        }

        // ---- online softmax ----
#pragma unroll
        for (int rh = 0; rh < 2; rh++) {
            float mx = -1e30f;
#pragma unroll
            for (int nt = 0; nt < 8; nt++)
                mx = fmaxf(mx, fmaxf(S[nt][rh * 2], S[nt][rh * 2 + 1]));
            mx = fmaxf(mx, __shfl_xor_sync(0xffffffffu, mx, 1));
            mx = fmaxf(mx, __shfl_xor_sync(0xffffffffu, mx, 2));
            float mnew = fmaxf(mr[rh], mx);
            float corr = ex2f(mr[rh] - mnew);
            mr[rh] = mnew;
            float sum = 0.f;
#pragma unroll
            for (int nt = 0; nt < 8; nt++) {
                float p0 = ex2f(S[nt][rh * 2]     - mnew);
                float p1 = ex2f(S[nt][rh * 2 + 1] - mnew);
                S[nt][rh * 2] = p0; S[nt][rh * 2 + 1] = p1;
                sum += p0 + p1;
            }
            sum += __shfl_xor_sync(0xffffffffu, sum, 1);
            sum += __shfl_xor_sync(0xffffffffu, sum, 2);
            lr[rh] = lr[rh] * corr + sum;
#pragma unroll
            for (int nt = 0; nt < 8; nt++) {
                O[nt][rh * 2]     *= corr;
                O[nt][rh * 2 + 1] *= corr;
            }
        }

        // ---- O += P V (per-kc fragment build) ----
#pragma unroll
        for (int kc = 0; kc < 4; kc++) {
            uint32_t ph[4], pl[4];
#pragma unroll
            for (int half = 0; half < 2; half++) {
                int nt = 2 * kc + half;
                uint32_t u0 = __float_as_uint(S[nt][0]);
                uint32_t u1 = __float_as_uint(S[nt][1]);
                uint32_t u2 = __float_as_uint(S[nt][2]);
                uint32_t u3 = __float_as_uint(S[nt][3]);
                ph[half * 2 + 0] = __byte_perm(u0, u1, 0x7632);
                ph[half * 2 + 1] = __byte_perm(u2, u3, 0x7632);
                float q0 = S[nt][0] - __uint_as_float(u0 & 0xFFFF0000u);
                float q1 = S[nt][1] - __uint_as_float(u1 & 0xFFFF0000u);
                float q2 = S[nt][2] - __uint_as_float(u2 & 0xFFFF0000u);
                float q3 = S[nt][3] - __uint_as_float(u3 & 0xFFFF0000u);
                pl[half * 2 + 0] = pack_bf16x2(q0, q1);
                pl[half * 2 + 1] = pack_bf16x2(q2, q3);
            }
            uint32_t vh2[2], vl2[2];
#pragma unroll
            for (int nt = 0; nt < 8; nt++) {
                int row = nt * 8 + brow;
                uint32_t off = (uint32_t)(row * APITCH + (kc * 16 + bkoff) * 2);
                ldmat_x2(vh2, sb + SVH + off);
                ldmat_x2(vl2, sb + SVL + off);
                mma_bf16(O[nt], ph, vh2);
                mma_bf16(O[nt], pl, vh2);
                mma_bf16(O[nt], ph, vl2);
            }
        }

        }  // warp-level skip

        __syncthreads();   // all warps done with K/V smem before next load
    }

    // ---- normalize + write trunc-split Y ----
    {
        float i0 = 1.f / lr[0];
        float i1 = 1.f / lr[1];
        int r0 = r0w + g4;
#pragma unroll
        for (int nt = 0; nt < 8; nt++) {
            int col = h * HD + nt * 8 + 2 * t4;
            float f0 = O[nt][0] * i0, f1 = O[nt][1] * i0;
            uint32_t u0 = __float_as_uint(f0), u1 = __float_as_uint(f1);
            size_t off0 = ((size_t)b * TT + r0) * CC + col;
            *(uint32_t*)((uint16_t*)g_Yh + off0) = __byte_perm(u0, u1, 0x7632);
            *(uint32_t*)((uint16_t*)g_Yl + off0) =
                pack_bf16x2(f0 - __uint_as_float(u0 & 0xFFFF0000u),
                            f1 - __uint_as_float(u1 & 0xFFFF0000u));
            float f2 = O[nt][2] * i1, f3 = O[nt][3] * i1;
            uint32_t u2 = __float_as_uint(f2), u3 = __float_as_uint(f3);
            size_t off1 = ((size_t)b * TT + r0 + 8) * CC + col;
            *(uint32_t*)((uint16_t*)g_Yh + off1) = __byte_perm(u2, u3, 0x7632);
            *(uint32_t*)((uint16_t*)g_Yl + off1) =
                pack_bf16x2(f2 - __uint_as_float(u2 & 0xFFFF0000u),
                            f3 - __uint_as_float(u3 & 0xFFFF0000u));
        }
    }
}

// ---------------------------------------------------------------------------
extern "C" void kernel_launch(void* const* d_in, const int* in_sizes, int n_in,
                              void* d_out, int out_size)
{
    const float* x  = (const float*)d_in[0];
    const float* Wq = (const float*)d_in[1];
    const float* bq = (const float*)d_in[2];
    const float* Wk = (const float*)d_in[3];
    const float* bk = (const float*)d_in[4];
    const float* Wv = (const float*)d_in[5];
    const float* bv = (const float*)d_in[6];
    const float* Wp = (const float*)d_in[7];
    const float* bp = (const float*)d_in[8];
    float* out = (float*)d_out;

    __nv_bfloat16 *Xh, *Xl, *Qh, *Ql, *Kh, *Kl, *Vth, *Vtl, *Yh, *Yl, *Wth, *Wtl;
    cudaGetSymbolAddress((void**)&Xh,  g_Xh);
    cudaGetSymbolAddress((void**)&Xl,  g_Xl);
    cudaGetSymbolAddress((void**)&Qh,  g_Qh);
    cudaGetSymbolAddress((void**)&Ql,  g_Ql);
    cudaGetSymbolAddress((void**)&Kh,  g_Kh);
    cudaGetSymbolAddress((void**)&Kl,  g_Kl);
    cudaGetSymbolAddress((void**)&Vth, g_Vth);
    cudaGetSymbolAddress((void**)&Vtl, g_Vtl);
    cudaGetSymbolAddress((void**)&Yh,  g_Yh);
    cudaGetSymbolAddress((void**)&Yl,  g_Yl);
    cudaGetSymbolAddress((void**)&Wth, g_Wth);
    cudaGetSymbolAddress((void**)&Wtl, g_Wtl);

    cudaFuncSetAttribute(gemm_qkv_kernel,
                         cudaFuncAttributeMaxDynamicSharedMemorySize, GEMM_SMEM);
    cudaFuncSetAttribute(gemm_proj_kernel,
                         cudaFuncAttributeMaxDynamicSharedMemorySize, GEMM_SMEM);
    cudaFuncSetAttribute(attn_mma_kernel,
                         cudaFuncAttributeMaxDynamicSharedMemorySize, ATTN_SMEM);

    const size_t WSZ = (size_t)CC * CC;

    // 1) split x into bf16 hi/lo
    convert_split_kernel<<<1024, 256>>>(x, Xh, Xl, MM * CC / 4);

    // 2) transpose+split the 4 weights (one launch, grid.z = 4)
    dim3 tgrd(CC / 32, CC / 32, 4), tblk(32, 8);
    transpose_split_kernel<<<tgrd, tblk>>>(Wq, Wk, Wv, Wp, Wth, Wtl);

    // 3) fused Q/K/V projections (one launch, grid.z = 3)
    dim3 qkvgrd(CC / 128, MM / 128, 3);
    gemm_qkv_kernel<<<qkvgrd, 256, GEMM_SMEM>>>(Xh, Xl, Wth, Wtl, bq, bk, bv,
                                                Qh, Ql, Kh, Kl, Vth, Vtl);

    // 4) tensor-core flash attention (8 warps x 16 rows, 2 CTAs/SM target)
    dim3 agrd(TT / 128, HH, BB);
    attn_mma_kernel<<<agrd, 256, ATTN_SMEM>>>(Qh, Ql, Kh, Kl, Vth, Vtl);

    // 5) output projection (fp32 out)
    dim3 ggrd(CC / 128, MM / 128);
    gemm_proj_kernel<<<ggrd, 256, GEMM_SMEM>>>(Yh, Yl, Wth + 3*WSZ, Wtl + 3*WSZ, bp, out);

    (void)in_sizes; (void)n_in; (void)out_size;
}

// round 16
// speedup vs baseline: 1.0525x; 1.0433x over previous
#include <cuda_runtime.h>
#include <cuda_bf16.h>
#include <cstdint>

// Problem constants
#define BB 2
#define TT 2048
#define CC 1024
#define HH 16
#define HD 64
#define MM (BB*TT)   // 4096 rows

// 0.125 (1/sqrt(64)) * log2(e), folded into Q projection
#define SCALE_Q 0.18033688f

// ---------------------------------------------------------------------------
// Scratch (__device__ globals: allocation-free rule)
// ---------------------------------------------------------------------------
__device__ __nv_bfloat16 g_Xh[(size_t)MM*CC];
__device__ __nv_bfloat16 g_Xl[(size_t)MM*CC];
__device__ __nv_bfloat16 g_Qh[(size_t)MM*CC];
__device__ __nv_bfloat16 g_Ql[(size_t)MM*CC];
__device__ __nv_bfloat16 g_Kh[(size_t)MM*CC];
__device__ __nv_bfloat16 g_Kl[(size_t)MM*CC];
__device__ __nv_bfloat16 g_Vth[(size_t)MM*CC];  // V transposed per head [b,h,d,t]
__device__ __nv_bfloat16 g_Vtl[(size_t)MM*CC];
__device__ __nv_bfloat16 g_Yh[(size_t)MM*CC];
__device__ __nv_bfloat16 g_Yl[(size_t)MM*CC];
__device__ __nv_bfloat16 g_Wth[(size_t)4*CC*CC];
__device__ __nv_bfloat16 g_Wtl[(size_t)4*CC*CC];

// ---------------------------------------------------------------------------
// PTX helpers
// ---------------------------------------------------------------------------
__device__ __forceinline__ uint32_t smem_u32(const void* p) {
    uint32_t a;
    asm("{ .reg .u64 t; cvta.to.shared.u64 t, %1; cvt.u32.u64 %0, t; }" : "=r"(a) : "l"(p));
    return a;
}
__device__ __forceinline__ void cp_async16(uint32_t saddr, const void* gaddr) {
    asm volatile("cp.async.ca.shared.global [%0], [%1], 16;" :: "r"(saddr), "l"(gaddr));
}
#define CP_COMMIT() asm volatile("cp.async.commit_group;" ::: "memory")

__device__ __forceinline__ void ldmat_x4(uint32_t* r, uint32_t addr) {
    asm volatile("ldmatrix.sync.aligned.m8n8.x4.shared.b16 {%0,%1,%2,%3}, [%4];"
        : "=r"(r[0]), "=r"(r[1]), "=r"(r[2]), "=r"(r[3]) : "r"(addr));
}
__device__ __forceinline__ void ldmat_x2(uint32_t* r, uint32_t addr) {
    asm volatile("ldmatrix.sync.aligned.m8n8.x2.shared.b16 {%0,%1}, [%2];"
        : "=r"(r[0]), "=r"(r[1]) : "r"(addr));
}
__device__ __forceinline__ void mma_bf16(float* c, const uint32_t* a, const uint32_t* b) {
    asm volatile("mma.sync.aligned.m16n8k16.row.col.f32.bf16.bf16.f32 "
        "{%0,%1,%2,%3}, {%4,%5,%6,%7}, {%8,%9}, {%0,%1,%2,%3};"
        : "+f"(c[0]), "+f"(c[1]), "+f"(c[2]), "+f"(c[3])
        : "r"(a[0]), "r"(a[1]), "r"(a[2]), "r"(a[3]), "r"(b[0]), "r"(b[1]));
}
__device__ __forceinline__ uint32_t pack_bf16x2(float lo, float hi) {
    uint32_t d;
    asm("cvt.rn.satfinite.bf16x2.f32 %0, %1, %2;" : "=r"(d) : "f"(hi), "f"(lo));
    return d;
}
__device__ __forceinline__ float ex2f(float x) {
    float y; asm("ex2.approx.f32 %0, %1;" : "=f"(y) : "f"(x)); return y;
}

// ---------------------------------------------------------------------------
// Split-precision conversion kernels
// ---------------------------------------------------------------------------
__device__ __forceinline__ void split_bf16(float v, __nv_bfloat16& h, __nv_bfloat16& l) {
    h = __float2bfloat16(v);
    l = __float2bfloat16(v - __bfloat162float(h));
}

__global__ void convert_split_kernel(const float* __restrict__ in,
                                     __nv_bfloat16* __restrict__ oh,
                                     __nv_bfloat16* __restrict__ ol, int n4)
{
    for (int i = blockIdx.x * blockDim.x + threadIdx.x; i < n4; i += gridDim.x * blockDim.x) {
        float4 v = ((const float4*)in)[i];
        __nv_bfloat16 h0,l0,h1,l1,h2,l2,h3,l3;
        split_bf16(v.x,h0,l0); split_bf16(v.y,h1,l1);
        split_bf16(v.z,h2,l2); split_bf16(v.w,h3,l3);
        ((__nv_bfloat162*)oh)[2*i]   = __halves2bfloat162(h0,h1);
        ((__nv_bfloat162*)oh)[2*i+1] = __halves2bfloat162(h2,h3);
        ((__nv_bfloat162*)ol)[2*i]   = __halves2bfloat162(l0,l1);
        ((__nv_bfloat162*)ol)[2*i+1] = __halves2bfloat162(l2,l3);
    }
}

// 4 weights W[K,N] -> Wt[N,K] split into hi/lo bf16; grid.z selects weight
__global__ void transpose_split_kernel(
    const float* __restrict__ W0, const float* __restrict__ W1,
    const float* __restrict__ W2, const float* __restrict__ W3,
    __nv_bfloat16* __restrict__ Th, __nv_bfloat16* __restrict__ Tl)
{
    __shared__ float t[32][33];
    const int z = blockIdx.z;
    const float* W = (z == 0) ? W0 : (z == 1) ? W1 : (z == 2) ? W2 : W3;
    __nv_bfloat16* Thz = Th + (size_t)z * CC * CC;
    __nv_bfloat16* Tlz = Tl + (size_t)z * CC * CC;
    int xi = blockIdx.x * 32 + threadIdx.x;
    int yi = blockIdx.y * 32 + threadIdx.y;
#pragma unroll
    for (int j = 0; j < 32; j += 8)
        t[threadIdx.y + j][threadIdx.x] = W[(size_t)(yi + j) * CC + xi];
    __syncthreads();
    int xo = blockIdx.y * 32 + threadIdx.x;
    int yo = blockIdx.x * 32 + threadIdx.y;
#pragma unroll
    for (int j = 0; j < 32; j += 8) {
        float v = t[threadIdx.x][threadIdx.y + j];
        __nv_bfloat16 h, l;
        split_bf16(v, h, l);
        Thz[(size_t)(yo + j) * CC + xo] = h;
        Tlz[(size_t)(yo + j) * CC + xo] = l;
    }
}

// ---------------------------------------------------------------------------
// GEMM core (device function): [4096,1024] = A @ Wt^T + bias, epilogue mode:
//   mode 0: fp32 row-major; mode 1: split bf16 row-major; mode 2: split + V-transpose
// B-fragments loaded pairwise via ldmatrix.x4 (lanes 0-15 tile nt, 16-31 tile nt+1).
// ---------------------------------------------------------------------------
#define BK 32
#define PITCH 40
#define TILE_BYTES (128 * PITCH * 2)
#define AH_OFF 0
#define AL_OFF (2 * TILE_BYTES)
#define BH_OFF (4 * TILE_BYTES)
#define BL_OFF (6 * TILE_BYTES)
#define GEMM_SMEM (8 * TILE_BYTES)     // 81920 B

__device__ __forceinline__ void gemm_core(
    const __nv_bfloat16* __restrict__ Ah, const __nv_bfloat16* __restrict__ Al,
    const __nv_bfloat16* __restrict__ Bh, const __nv_bfloat16* __restrict__ Bl,
    const float* __restrict__ bias,
    float* __restrict__ outf,
    __nv_bfloat16* __restrict__ outh, __nv_bfloat16* __restrict__ outl,
    int mode, float scale, char* smem)
{
    const uint32_t sbase = smem_u32(smem);
    const int tid  = threadIdx.x;
    const int lane = tid & 31;
    const int wid  = tid >> 5;
    const int warp_m = wid >> 2;
    const int warp_n = wid & 3;

    const int rowBase = blockIdx.y * 128;
    const int colBase = blockIdx.x * 128;

    float acc[4][4][4];
#pragma unroll
    for (int i = 0; i < 4; i++)
#pragma unroll
        for (int j = 0; j < 4; j++)
#pragma unroll
            for (int r = 0; r < 4; r++) acc[i][j][r] = 0.f;

    auto load_stage = [&](int stg, int kc0) {
        const uint32_t so = (uint32_t)stg * TILE_BYTES;
#pragma unroll
        for (int it = 0; it < 2; it++) {
            int v = tid + it * 256;
            int r = v >> 2;
            int cv = v & 3;
            uint32_t doff = so + (uint32_t)(r * 80 + cv * 16);
            size_t gA = (size_t)(rowBase + r) * CC + kc0 + cv * 8;
            size_t gB = (size_t)(colBase + r) * CC + kc0 + cv * 8;
            cp_async16(sbase + AH_OFF + doff, Ah + gA);
            cp_async16(sbase + AL_OFF + doff, Al + gA);
            cp_async16(sbase + BH_OFF + doff, Bh + gB);
            cp_async16(sbase + BL_OFF + doff, Bl + gB);
        }
        CP_COMMIT();
    };

    const int arow  = (lane & 7) + ((lane >> 3) & 1) * 8;
    const int akoff = (lane >> 4) * 8;
    // x4 B-pair addressing: lanes 0-15 -> tile nt (pair low), 16-31 -> nt+1
    const int b4row = lane & 7;
    const int b4nt  = (lane >> 4) & 1;
    const int b4k   = ((lane >> 3) & 1) * 8;

    auto compute_stage = [&](int stg) {
        const uint32_t so = (uint32_t)stg * TILE_BYTES;
#pragma unroll
        for (int ks = 0; ks < 2; ks++) {
            const int k0 = ks * 16;
            uint32_t ah[4][4], al[4][4], bh[2][4], bl[2][4];
#pragma unroll
            for (int mt = 0; mt < 4; mt++) {
                int row = warp_m * 64 + mt * 16 + arow;
                uint32_t off = so + (uint32_t)(row * 80 + (k0 + akoff) * 2);
                ldmat_x4(ah[mt], sbase + AH_OFF + off);
                ldmat_x4(al[mt], sbase + AL_OFF + off);
            }
#pragma unroll
            for (int np = 0; np < 2; np++) {
                int row = warp_n * 32 + (np * 2 + b4nt) * 8 + b4row;
                uint32_t off = so + (uint32_t)(row * 80 + (k0 + b4k) * 2);
                ldmat_x4(bh[np], sbase + BH_OFF + off);
                ldmat_x4(bl[np], sbase + BL_OFF + off);
            }
#pragma unroll
            for (int mt = 0; mt < 4; mt++)
#pragma unroll
                for (int nt = 0; nt < 4; nt++) {
                    const uint32_t* bfh = &bh[nt >> 1][(nt & 1) * 2];
                    const uint32_t* bfl = &bl[nt >> 1][(nt & 1) * 2];
                    mma_bf16(acc[mt][nt], ah[mt], bfh);
                    mma_bf16(acc[mt][nt], ah[mt], bfl);
                    mma_bf16(acc[mt][nt], al[mt], bfh);
                }
        }
    };

    const int NCHUNK = CC / BK;
    load_stage(0, 0);
    for (int c = 0; c < NCHUNK; c++) {
        if (c + 1 < NCHUNK) {
            load_stage((c + 1) & 1, (c + 1) * BK);
            asm volatile("cp.async.wait_group 1;" ::: "memory");
        } else {
            asm volatile("cp.async.wait_group 0;" ::: "memory");
        }
        __syncthreads();
        compute_stage(c & 1);
        __syncthreads();
    }

    const int gg  = lane >> 2;
    const int tg2 = (lane & 3) * 2;
#pragma unroll
    for (int mt = 0; mt < 4; mt++) {
        int row0 = rowBase + warp_m * 64 + mt * 16 + gg;
#pragma unroll
        for (int nt = 0; nt < 4; nt++) {
            int col = colBase + warp_n * 32 + nt * 8 + tg2;
            float2 bv = *(const float2*)(bias + col);
            float o00 = (acc[mt][nt][0] + bv.x) * scale;
            float o01 = (acc[mt][nt][1] + bv.y) * scale;
            float o10 = (acc[mt][nt][2] + bv.x) * scale;
            float o11 = (acc[mt][nt][3] + bv.y) * scale;
            if (mode == 0) {
                *(float2*)(outf + (size_t)row0 * CC + col) = make_float2(o00, o01);
                *(float2*)(outf + (size_t)(row0 + 8) * CC + col) = make_float2(o10, o11);
            } else if (mode == 1) {
                uint32_t u0 = __float_as_uint(o00), u1 = __float_as_uint(o01);
                uint32_t u2 = __float_as_uint(o10), u3 = __float_as_uint(o11);
                uint16_t* oh16 = (uint16_t*)outh;
                uint16_t* ol16 = (uint16_t*)outl;
                *(uint32_t*)(oh16 + (size_t)row0 * CC + col) = __byte_perm(u0, u1, 0x7632);
                *(uint32_t*)(oh16 + (size_t)(row0 + 8) * CC + col) = __byte_perm(u2, u3, 0x7632);
                *(uint32_t*)(ol16 + (size_t)row0 * CC + col) =
                    pack_bf16x2(o00 - __uint_as_float(u0 & 0xFFFF0000u),
                                o01 - __uint_as_float(u1 & 0xFFFF0000u));
                *(uint32_t*)(ol16 + (size_t)(row0 + 8) * CC + col) =
                    pack_bf16x2(o10 - __uint_as_float(u2 & 0xFFFF0000u),
                                o11 - __uint_as_float(u3 & 0xFFFF0000u));
            } else {
                int hh = col >> 6, d = col & 63;
                int b0 = row0 >> 11, t0 = row0 & 2047;
                size_t base = (((size_t)b0 * HH + hh) * HD + d) * TT + t0;
                uint16_t* oh16 = (uint16_t*)outh;
                __nv_bfloat16* ol16 = outl;
                uint32_t u;
                u = __float_as_uint(o00);
                oh16[base] = (uint16_t)(u >> 16);
                ol16[base] = __float2bfloat16(o00 - __uint_as_float(u & 0xFFFF0000u));
                u = __float_as_uint(o01);
                oh16[base + TT] = (uint16_t)(u >> 16);
                ol16[base + TT] = __float2bfloat16(o01 - __uint_as_float(u & 0xFFFF0000u));
                u = __float_as_uint(o10);
                oh16[base + 8] = (uint16_t)(u >> 16);
                ol16[base + 8] = __float2bfloat16(o10 - __uint_as_float(u & 0xFFFF0000u));
                u = __float_as_uint(o11);
                oh16[base + TT + 8] = (uint16_t)(u >> 16);
                ol16[base + TT + 8] = __float2bfloat16(o11 - __uint_as_float(u & 0xFFFF0000u));
            }
        }
    }
}

// QKV fused: grid.z selects projection (0=Q scaled, 1=K, 2=V transposed)
__global__ __launch_bounds__(256) void gemm_qkv_kernel(
    const __nv_bfloat16* __restrict__ Xh, const __nv_bfloat16* __restrict__ Xl,
    const __nv_bfloat16* __restrict__ Wth, const __nv_bfloat16* __restrict__ Wtl,
    const float* __restrict__ bq, const float* __restrict__ bk, const float* __restrict__ bv,
    __nv_bfloat16* __restrict__ Qh, __nv_bfloat16* __restrict__ Ql,
    __nv_bfloat16* __restrict__ Kh, __nv_bfloat16* __restrict__ Kl,
    __nv_bfloat16* __restrict__ Vth, __nv_bfloat16* __restrict__ Vtl)
{
    extern __shared__ char smem[];
    const int z = blockIdx.z;
    const size_t WSZ = (size_t)CC * CC;
    const __nv_bfloat16* Bh = Wth + (size_t)z * WSZ;
    const __nv_bfloat16* Bl = Wtl + (size_t)z * WSZ;
    const float* bias = (z == 0) ? bq : (z == 1) ? bk : bv;
    __nv_bfloat16* oh = (z == 0) ? Qh : (z == 1) ? Kh : Vth;
    __nv_bfloat16* ol = (z == 0) ? Ql : (z == 1) ? Kl : Vtl;
    int mode = (z == 2) ? 2 : 1;
    float scale = (z == 0) ? SCALE_Q : 1.0f;
    gemm_core(Xh, Xl, Bh, Bl, bias, nullptr, oh, ol, mode, scale, smem);
}

// Output projection: fp32 out
__global__ __launch_bounds__(256) void gemm_proj_kernel(
    const __nv_bfloat16* __restrict__ Ah, const __nv_bfloat16* __restrict__ Al,
    const __nv_bfloat16* __restrict__ Bh, const __nv_bfloat16* __restrict__ Bl,
    const float* __restrict__ bias, float* __restrict__ outf)
{
    extern __shared__ char smem[];
    gemm_core(Ah, Al, Bh, Bl, bias, outf, nullptr, nullptr, 0, 1.0f, smem);
}

// ---------------------------------------------------------------------------
// Tensor-core causal flash attention.
// 256 threads, 8 warps x 16 q-rows (R13, regs=128, 2 CTAs/SM).
// R14: K and V fragments loaded pairwise via ldmatrix.x4 (halved LDS issues).
// ---------------------------------------------------------------------------
#define APITCH 144            // 72 bf16 per row (bytes)
#define SQH 0
#define SQL 18432
#define SKH 36864
#define SKL 46080
#define SVH 55296
#define SVL 64512
#define ATTN_SMEM 73728

__global__ __launch_bounds__(256, 2) void attn_mma_kernel(
    const __nv_bfloat16* __restrict__ Qh_, const __nv_bfloat16* __restrict__ Ql_,
    const __nv_bfloat16* __restrict__ Kh_, const __nv_bfloat16* __restrict__ Kl_,
    const __nv_bfloat16* __restrict__ Vh_, const __nv_bfloat16* __restrict__ Vl_)
{
    extern __shared__ char smem[];
    const uint32_t sb = smem_u32(smem);
    const int tid = threadIdx.x, lane = tid & 31, wid = tid >> 5;
    const int qb = gridDim.x - 1 - blockIdx.x;   // heavy blocks first
    const int h  = blockIdx.y, b = blockIdx.z;

    // Q tile: 128 rows x 64 bf16, hi/lo
#pragma unroll
    for (int i = 0; i < 4; i++) {
        int v = tid + i * 256, r = v >> 3, c = v & 7;
        uint32_t so = (uint32_t)(r * APITCH + c * 16);
        size_t g = ((size_t)b * TT + qb * 128 + r) * CC + h * HD + c * 8;
        cp_async16(sb + SQH + so, Qh_ + g);
        cp_async16(sb + SQL + so, Ql_ + g);
    }
    CP_COMMIT();

    const int g4 = lane >> 2, t4 = lane & 3;
    const int arow  = (lane & 7) + ((lane >> 3) & 1) * 8;
    const int akoff = (lane >> 4) * 8;
    // x4 pair addressing (lanes 0-15 -> tile nt, 16-31 -> nt+1)
    const int b4row = lane & 7;
    const int b4nt  = (lane >> 4) & 1;
    const int b4k   = ((lane >> 3) & 1) * 8;
    const int r0w = qb * 128 + wid * 16;   // this warp's first q row (16-row slice)

    float O[8][4];
#pragma unroll
    for (int nt = 0; nt < 8; nt++)
#pragma unroll
        for (int r = 0; r < 4; r++) O[nt][r] = 0.f;
    float mr[2] = {-1e30f, -1e30f};
    float lr[2] = {0.f, 0.f};

    const int nkv = qb * 2 + 2;
    for (int kb = 0; kb < nkv; kb++) {
        // K tile [64 keys][64 hd], Vt tile [64 hd][64 keys], hi/lo
#pragma unroll
        for (int i = 0; i < 2; i++) {
            int v = tid + i * 256, r = v >> 3, c = v & 7;
            uint32_t so = (uint32_t)(r * APITCH + c * 16);
            size_t gk = ((size_t)b * TT + kb * 64 + r) * CC + h * HD + c * 8;
            cp_async16(sb + SKH + so, Kh_ + gk);
            cp_async16(sb + SKL + so, Kl_ + gk);
            size_t gv = (((size_t)b * HH + h) * HD + r) * TT + kb * 64 + c * 8;
            cp_async16(sb + SVH + so, Vh_ + gv);
            cp_async16(sb + SVL + so, Vl_ + gv);
        }
        CP_COMMIT();
        asm volatile("cp.async.wait_group 0;" ::: "memory");
        __syncthreads();

        // warp-level skip: block entirely above this warp's 16 rows
        if (kb * 64 <= r0w + 15) {

        // ---- S = Q K^T ----
        float S[8][4];
#pragma unroll
        for (int nt = 0; nt < 8; nt++)
#pragma unroll
            for (int r = 0; r < 4; r++) S[nt][r] = 0.f;
#pragma unroll
        for (int kc = 0; kc < 4; kc++) {
            uint32_t ah[4], al[4], bh4[4][4], bl4[4][4];
            {
                int row = wid * 16 + arow;
                uint32_t off = (uint32_t)(row * APITCH + (kc * 16 + akoff) * 2);
                ldmat_x4(ah, sb + SQH + off);
                ldmat_x4(al, sb + SQL + off);
            }
#pragma unroll
            for (int np = 0; np < 4; np++) {
                int row = (np * 2 + b4nt) * 8 + b4row;
                uint32_t off = (uint32_t)(row * APITCH + (kc * 16 + b4k) * 2);
                ldmat_x4(bh4[np], sb + SKH + off);
                ldmat_x4(bl4[np], sb + SKL + off);
            }
#pragma unroll
            for (int nt = 0; nt < 8; nt++) {
                const uint32_t* bfh = &bh4[nt >> 1][(nt & 1) * 2];
                const uint32_t* bfl = &bl4[nt >> 1][(nt & 1) * 2];
                mma_bf16(S[nt], ah, bfh);
                mma_bf16(S[nt], ah, bfl);
                mma_bf16(S[nt], al, bfh);
            }
        }

        // ---- causal mask (diagonal-region blocks only) ----
        if (kb * 64 + 63 > r0w) {
            int r0 = r0w + g4;
#pragma unroll
            for (int nt = 0; nt < 8; nt++) {
                int k0 = kb * 64 + nt * 8 + 2 * t4;
                if (k0     > r0)     S[nt][0] = -1e30f;
                if (k0 + 1 > r0)     S[nt][1] = -1e30f;
                if (k0     > r0 + 8) S[nt][2] = -1e30f;
                if (k0 + 1 > r0 + 8) S[nt][3] = -1e30f;
            }
        }

        // ---- online softmax ----
#pragma unroll
        for (int rh = 0; rh < 2; rh++) {
            float mx = -1e30f;
#pragma unroll
            for (int nt = 0; nt < 8; nt++)
                mx = fmaxf(mx, fmaxf(S[nt][rh * 2], S[nt][rh * 2 + 1]));
            mx = fmaxf(mx, __shfl_xor_sync(0xffffffffu, mx, 1));
            mx = fmaxf(mx, __shfl_xor_sync(0xffffffffu, mx, 2));
            float mnew = fmaxf(mr[rh], mx);
            float corr = ex2f(mr[rh] - mnew);
            mr[rh] = mnew;
            float sum = 0.f;
#pragma unroll
            for (int nt = 0; nt < 8; nt++) {
                float p0 = ex2f(S[nt][rh * 2]     - mnew);
                float p1 = ex2f(S[nt][rh * 2 + 1] - mnew);
                S[nt][rh * 2] = p0; S[nt][rh * 2 + 1] = p1;
                sum += p0 + p1;
            }
            sum += __shfl_xor_sync(0xffffffffu, sum, 1);
            sum += __shfl_xor_sync(0xffffffffu, sum, 2);
            lr[rh] = lr[rh] * corr + sum;
#pragma unroll
            for (int nt = 0; nt < 8; nt++) {
                O[nt][rh * 2]     *= corr;
                O[nt][rh * 2 + 1] *= corr;
            }
        }

        // ---- O += P V (per-kc fragment build; V pairs via x4) ----
#pragma unroll
        for (int kc = 0; kc < 4; kc++) {
            uint32_t ph[4], pl[4];
#pragma unroll
            for (int half = 0; half < 2; half++) {
                int nt = 2 * kc + half;
                uint32_t u0 = __float_as_uint(S[nt][0]);
                uint32_t u1 = __float_as_uint(S[nt][1]);
                uint32_t u2 = __float_as_uint(S[nt][2]);
                uint32_t u3 = __float_as_uint(S[nt][3]);
                ph[half * 2 + 0] = __byte_perm(u0, u1, 0x7632);
                ph[half * 2 + 1] = __byte_perm(u2, u3, 0x7632);
                float q0 = S[nt][0] - __uint_as_float(u0 & 0xFFFF0000u);
                float q1 = S[nt][1] - __uint_as_float(u1 & 0xFFFF0000u);
                float q2 = S[nt][2] - __uint_as_float(u2 & 0xFFFF0000u);
                float q3 = S[nt][3] - __uint_as_float(u3 & 0xFFFF0000u);
                pl[half * 2 + 0] = pack_bf16x2(q0, q1);
                pl[half * 2 + 1] = pack_bf16x2(q2, q3);
            }
#pragma unroll
            for (int np = 0; np < 4; np++) {
                uint32_t vh4[4], vl4[4];
                int row = (np * 2 + b4nt) * 8 + b4row;
                uint32_t off = (uint32_t)(row * APITCH + (kc * 16 + b4k) * 2);
                ldmat_x4(vh4, sb + SVH + off);
                ldmat_x4(vl4, sb + SVL + off);
                mma_bf16(O[2 * np],     ph, vh4);
                mma_bf16(O[2 * np],     pl, vh4);
                mma_bf16(O[2 * np],     ph, vl4);
                mma_bf16(O[2 * np + 1], ph, vh4 + 2);
                mma_bf16(O[2 * np + 1], pl, vh4 + 2);
                mma_bf16(O[2 * np + 1], ph, vl4 + 2);
            }
        }

        }  // warp-level skip

        __syncthreads();   // all warps done with K/V smem before next load
    }

    // ---- normalize + write trunc-split Y ----
    {
        float i0 = 1.f / lr[0];
        float i1 = 1.f / lr[1];
        int r0 = r0w + g4;
#pragma unroll
        for (int nt = 0; nt < 8; nt++) {
            int col = h * HD + nt * 8 + 2 * t4;
            float f0 = O[nt][0] * i0, f1 = O[nt][1] * i0;
            uint32_t u0 = __float_as_uint(f0), u1 = __float_as_uint(f1);
            size_t off0 = ((size_t)b * TT + r0) * CC + col;
            *(uint32_t*)((uint16_t*)g_Yh + off0) = __byte_perm(u0, u1, 0x7632);
            *(uint32_t*)((uint16_t*)g_Yl + off0) =
                pack_bf16x2(f0 - __uint_as_float(u0 & 0xFFFF0000u),
                            f1 - __uint_as_float(u1 & 0xFFFF0000u));
            float f2 = O[nt][2] * i1, f3 = O[nt][3] * i1;
            uint32_t u2 = __float_as_uint(f2), u3 = __float_as_uint(f3);
            size_t off1 = ((size_t)b * TT + r0 + 8) * CC + col;
            *(uint32_t*)((uint16_t*)g_Yh + off1) = __byte_perm(u2, u3, 0x7632);
            *(uint32_t*)((uint16_t*)g_Yl + off1) =
                pack_bf16x2(f2 - __uint_as_float(u2 & 0xFFFF0000u),
                            f3 - __uint_as_float(u3 & 0xFFFF0000u));
        }
    }
}

// ---------------------------------------------------------------------------
extern "C" void kernel_launch(void* const* d_in, const int* in_sizes, int n_in,
                              void* d_out, int out_size)
{
    const float* x  = (const float*)d_in[0];
    const float* Wq = (const float*)d_in[1];
    const float* bq = (const float*)d_in[2];
    const float* Wk = (const float*)d_in[3];
    const float* bk = (const float*)d_in[4];
    const float* Wv = (const float*)d_in[5];
    const float* bv = (const float*)d_in[6];
    const float* Wp = (const float*)d_in[7];
    const float* bp = (const float*)d_in[8];
    float* out = (float*)d_out;

    __nv_bfloat16 *Xh, *Xl, *Qh, *Ql, *Kh, *Kl, *Vth, *Vtl, *Yh, *Yl, *Wth, *Wtl;
    cudaGetSymbolAddress((void**)&Xh,  g_Xh);
    cudaGetSymbolAddress((void**)&Xl,  g_Xl);
    cudaGetSymbolAddress((void**)&Qh,  g_Qh);
    cudaGetSymbolAddress((void**)&Ql,  g_Ql);
    cudaGetSymbolAddress((void**)&Kh,  g_Kh);
    cudaGetSymbolAddress((void**)&Kl,  g_Kl);
    cudaGetSymbolAddress((void**)&Vth, g_Vth);
    cudaGetSymbolAddress((void**)&Vtl, g_Vtl);
    cudaGetSymbolAddress((void**)&Yh,  g_Yh);
    cudaGetSymbolAddress((void**)&Yl,  g_Yl);
    cudaGetSymbolAddress((void**)&Wth, g_Wth);
    cudaGetSymbolAddress((void**)&Wtl, g_Wtl);

    cudaFuncSetAttribute(gemm_qkv_kernel,
                         cudaFuncAttributeMaxDynamicSharedMemorySize, GEMM_SMEM);
    cudaFuncSetAttribute(gemm_proj_kernel,
                         cudaFuncAttributeMaxDynamicSharedMemorySize, GEMM_SMEM);
    cudaFuncSetAttribute(attn_mma_kernel,
                         cudaFuncAttributeMaxDynamicSharedMemorySize, ATTN_SMEM);

    const size_t WSZ = (size_t)CC * CC;

    // 1) split x into bf16 hi/lo
    convert_split_kernel<<<1024, 256>>>(x, Xh, Xl, MM * CC / 4);

    // 2) transpose+split the 4 weights (one launch, grid.z = 4)
    dim3 tgrd(CC / 32, CC / 32, 4), tblk(32, 8);
    transpose_split_kernel<<<tgrd, tblk>>>(Wq, Wk, Wv, Wp, Wth, Wtl);

    // 3) fused Q/K/V projections (one launch, grid.z = 3)
    dim3 qkvgrd(CC / 128, MM / 128, 3);
    gemm_qkv_kernel<<<qkvgrd, 256, GEMM_SMEM>>>(Xh, Xl, Wth, Wtl, bq, bk, bv,
                                                Qh, Ql, Kh, Kl, Vth, Vtl);

    // 4) tensor-core flash attention (8 warps x 16 rows, x4 fragment pairing)
    dim3 agrd(TT / 128, HH, BB);
    attn_mma_kernel<<<agrd, 256, ATTN_SMEM>>>(Qh, Ql, Kh, Kl, Vth, Vtl);

    // 5) output projection (fp32 out)
    dim3 ggrd(CC / 128, MM / 128);
    gemm_proj_kernel<<<ggrd, 256, GEMM_SMEM>>>(Yh, Yl, Wth + 3*WSZ, Wtl + 3*WSZ, bp, out);

    (void)in_sizes; (void)n_in; (void)out_size;
}